// round 15
// baseline (speedup 1.0000x reference)
#include <cuda_runtime.h>
#include <cuda_bf16.h>
#include <cstdint>

// RFFT2d: x (32,1,1024,1024) fp32 -> out (32, 16384, 8, 5, 2) fp32
// 8x8 blocks, length-8 rFFT along each block row, scaled by 1/64.
//
// Persistent CTAs (1184, ~8/SM) grid-striding over 16384 tiles of 256 rows.
// Dense warp loads (each LDG.128 covers 4 fully-consumed 128B lines) + shfl
// redistribution. Double-buffered 10KB smem staging: tile i's compute/STS
// overlaps tile i-1's 10KB cp.async.bulk drain; wait_group 1 before reuse.

#define TOTAL_ROWS  (32u * 128u * 128u * 8u)  // 4,194,304
#define ROWS_PER_TILE 256u
#define NUM_TILES     (TOTAL_ROWS / ROWS_PER_TILE)  // 16384
#define BUF_FLOATS    (ROWS_PER_TILE * 10u)         // 2560 floats = 10240 B
#define GRID_CTAS     1184u

__device__ __forceinline__ float4 shfl4(float4 v, unsigned src) {
    float4 r;
    r.x = __shfl_sync(0xffffffffu, v.x, src);
    r.y = __shfl_sync(0xffffffffu, v.y, src);
    r.z = __shfl_sync(0xffffffffu, v.z, src);
    r.w = __shfl_sync(0xffffffffu, v.w, src);
    return r;
}

__device__ __forceinline__ void rfft8_row(float4 v0, float4 v1, float* sm_row)
{
    float x0 = v0.x, x1 = v0.y, x2 = v0.z, x3 = v0.w;
    float x4 = v1.x, x5 = v1.y, x6 = v1.z, x7 = v1.w;

    const float s   = 0.70710678118654752440f;
    const float scl = 1.0f / 64.0f;

    float a = x0 + x4, b = x0 - x4;
    float c = x2 + x6, d = x2 - x6;
    float e = x1 + x5, f = x1 - x5;
    float g = x3 + x7, h = x3 - x7;

    float fmh = f - h;
    float fph = f + h;

    float X0r = (a + c) + (e + g);
    float X4r = (a + c) - (e + g);
    float X2r = a - c;
    float X2i = g - e;
    float sfmh = s * fmh;
    float sfph = s * fph;
    float X1r = b + sfmh;
    float X1i = -sfph - d;
    float X3r = b - sfmh;
    float X3i = d - sfph;

    float2* so = reinterpret_cast<float2*>(sm_row);
    so[0] = make_float2(X0r * scl, 0.0f);
    so[1] = make_float2(X1r * scl, X1i * scl);
    so[2] = make_float2(X2r * scl, X2i * scl);
    so[3] = make_float2(X3r * scl, X3i * scl);
    so[4] = make_float2(X4r * scl, 0.0f);
}

__global__ __launch_bounds__(256) void rfft8_kernel(
    const float* __restrict__ in, float* __restrict__ out)
{
    __shared__ __align__(16) float sm[2u * BUF_FLOATS];  // 20480 B

    unsigned t = threadIdx.x;
    unsigned w = t >> 5;     // warp 0..7
    unsigned l = t & 31u;    // lane

    // Per-thread routing constants (tile-invariant).
    unsigned s0 = (l & 3u) * 8u + ((l >> 3) << 1);
    unsigned s1 = s0 + 1u;
    bool lo = (l & 4u) == 0u;

    uint32_t sbase;
    asm("{ .reg .u64 tmp; cvta.to.shared.u64 tmp, %1; cvt.u32.u64 %0, tmp; }"
        : "=r"(sbase) : "l"(sm));

    const float4* in4 = reinterpret_cast<const float4*>(in);
    unsigned p = 0;

    for (unsigned T = blockIdx.x; T < NUM_TILES; T += gridDim.x) {
        unsigned nbh = T >> 2;       // n*128 + bh (4 tiles per 1024-row stripe)
        unsigned q   = T & 3u;       // quarter within stripe (32 blocks each)

        // Dense load: lane l reads float4 (l&7) of image row (l>>3) within
        // this warp's 4-block span. 8 lanes fully consume one 128B line.
        unsigned a00 = (nbh * 8u + (l >> 3)) * 256u + q * 64u + w * 8u + (l & 7u);
        float4 L0 = in4[a00];            // image rows 0..3 of stripe
        float4 L1 = in4[a00 + 1024u];    // image rows 4..7

        float* buf = sm + p * BUF_FLOATS;

        // Ensure this buffer's previous bulk store (iter i-2) has drained.
        if (t == 0) {
            asm volatile("cp.async.bulk.wait_group 1;" ::: "memory");
        }
        __syncthreads();

        // Route to owning thread: r_own = l&7 fastest, one row per thread.
        {
            float4 A = shfl4(L0, s0);
            float4 Bv = shfl4(L0, s1);
            float4 C = shfl4(L1, s0);
            float4 D = shfl4(L1, s1);
            float4 v0 = lo ? A : C;
            float4 v1 = lo ? Bv : D;
            rfft8_row(v0, v1, buf + t * 10u);
        }

        asm volatile("fence.proxy.async.shared::cta;" ::: "memory");
        __syncthreads();

        if (t == 0) {
            float* dst = out + (size_t)T * BUF_FLOATS;
            asm volatile(
                "cp.async.bulk.global.shared::cta.bulk_group [%0], [%1], %2;"
                :: "l"(dst), "r"(sbase + p * (BUF_FLOATS * 4u)),
                   "r"(BUF_FLOATS * 4u) : "memory");
            asm volatile("cp.async.bulk.commit_group;" ::: "memory");
            // no wait here: drain overlaps next tile's loads + compute
        }
        p ^= 1u;
    }

    // All outstanding bulk stores must land before CTA teardown frees smem.
    if (t == 0) {
        asm volatile("cp.async.bulk.wait_group 0;" ::: "memory");
    }
}

extern "C" void kernel_launch(void* const* d_in, const int* in_sizes, int n_in,
                              void* d_out, int out_size)
{
    const float* x = (const float*)d_in[0];
    float* out = (float*)d_out;
    rfft8_kernel<<<GRID_CTAS, 256>>>(x, out);
}